// round 16
// baseline (speedup 1.0000x reference)
#include <cuda_runtime.h>
#include <math_constants.h>

// Problem constants
#define B_   256
#define P_   128
#define KD   512
#define HE_  1024
#define HF_  512
#define HID_ 64
#define EMB  (KD + 2*HF_)   // 1536

#define KC_  16   // bias split-k chunks of 128 over 2048
#define BG_  8

typedef unsigned long long u64;
typedef unsigned int u32;

// Scratch: split-k partials for bias[b][h] = x_b @ W1qf
__device__ float g_part[KC_][B_][HID_];

__device__ __forceinline__ u64 ffma2(u64 a, u64 b, u64 c) {
    u64 d;
    asm("fma.rn.f32x2 %0, %1, %2, %3;" : "=l"(d) : "l"(a), "l"(b), "l"(c));
    return d;
}
__device__ __forceinline__ u64 dup2(float x) {
    u64 d; unsigned r = __float_as_uint(x);
    asm("mov.b64 %0, {%1, %1};" : "=l"(d) : "r"(r));
    return d;
}
__device__ __forceinline__ void unpack2(u64 v, float& lo, float& hi) {
    unsigned l, h;
    asm("mov.b64 {%0, %1}, %2;" : "=r"(l), "=r"(h) : "l"(v));
    lo = __uint_as_float(l); hi = __uint_as_float(h);
}

// ---------------------------------------------------------------------------
// Kernel 1: split-K bias partials (unchanged — proven, ~3us).
// ---------------------------------------------------------------------------
__global__ void __launch_bounds__(256) bias_kernel(
    const float* __restrict__ query,
    const float* __restrict__ frame,
    const float* __restrict__ W1)
{
    const int kc = blockIdx.x;
    const int bg = blockIdx.y;
    const int j0 = kc * 128;
    const int b0 = bg * 32;
    const int tid = threadIdx.x;

    __shared__ __align__(16) float ws[128][HID_];
    __shared__ __align__(16) float xs[32][128];

    {
        const float4* src = reinterpret_cast<const float4*>(W1 + (size_t)(KD + j0) * HID_);
        float4* dst = reinterpret_cast<float4*>(&ws[0][0]);
        #pragma unroll
        for (int i = 0; i < 8; i++) dst[tid + 256 * i] = src[tid + 256 * i];
    }
    {
        const float* xsrc = (j0 < HE_) ? (query + (size_t)b0 * HE_ + j0)
                                       : (frame + (size_t)b0 * (2 * HF_) + (j0 - HE_));
        #pragma unroll
        for (int i = 0; i < 4; i++) {
            int fid = tid + 256 * i;
            int r = fid >> 5, c4 = (fid & 31) << 2;
            *reinterpret_cast<float4*>(&xs[r][c4]) =
                *reinterpret_cast<const float4*>(xsrc + (size_t)r * 1024 + c4);
        }
    }
    __syncthreads();

    const int h  = tid & 63;
    const int bq = tid >> 6;

    float acc[8];
    #pragma unroll
    for (int i = 0; i < 8; i++) acc[i] = 0.f;

    for (int kk0 = 0; kk0 < 128; kk0 += 4) {
        float w0 = ws[kk0 + 0][h], w1 = ws[kk0 + 1][h];
        float w2 = ws[kk0 + 2][h], w3 = ws[kk0 + 3][h];
        #pragma unroll
        for (int i = 0; i < 8; i++) {
            float4 x = *reinterpret_cast<const float4*>(&xs[bq * 8 + i][kk0]);
            acc[i] = fmaf(x.x, w0, acc[i]);
            acc[i] = fmaf(x.y, w1, acc[i]);
            acc[i] = fmaf(x.z, w2, acc[i]);
            acc[i] = fmaf(x.w, w3, acc[i]);
        }
    }
    #pragma unroll
    for (int i = 0; i < 8; i++)
        g_part[kc][b0 + bq * 8 + i][h] = acc[i];
}

// ---------------------------------------------------------------------------
// Dynamic smem layout for score_kernel.
// sA: f32 [32][132] per stage; sB2: pre-DUPLICATED u64 [32][64] per stage.
// red aliases stage-0 sA (free after last chunk computes stage 1).
// ---------------------------------------------------------------------------
#define SA_STRIDE 132
#define OFF_SA(s)  ((s) * 16896)                 // 32*132*4 each
#define OFF_SB2(s) (33792 + (s) * 16384)         // 32*64*8 each
#define OFF_RED    OFF_SA(0)                     // aliased: 128*17*4 = 8704
#define OFF_BIAS   66560                         // 64 f32
#define OFF_W2     66816                         // 64 f32
#define OFF_RTMP   67072                         // 4 f32
#define OFF_WSM    67088                         // 128 f32
#define SMEM_DYN   67616

// ---------------------------------------------------------------------------
// Kernel 2: per-batch scores + masked softmax + context (fused).
// One CTA per batch, 256 threads. C-tile 128p x 64h; each thread owns an
// 8p x 4h micro-tile as 16 f32x2 accumulators packed along p-pairs.
// B is pre-duplicated in smem -> inner loop is 4 LDS.128 + 16 FFMA2, no MOVs.
// ---------------------------------------------------------------------------
__global__ void __launch_bounds__(256, 2) score_kernel(
    const float* __restrict__ keys,
    const float* __restrict__ frame,
    const int*   __restrict__ mask,
    const float* __restrict__ W1,
    const float* __restrict__ W2,
    float*       __restrict__ out)
{
    extern __shared__ __align__(16) char smem[];
    const int b   = blockIdx.x;
    const int tid = threadIdx.x;
    const int tx  = tid & 15;   // h-block: h0 = tx*4
    const int ty  = tid >> 4;   // p-block: p0 = ty*8 (0..15)

    float* bias_s = (float*)(smem + OFF_BIAS);
    float* w2_s   = (float*)(smem + OFF_W2);
    float* rtmp   = (float*)(smem + OFF_RTMP);
    float* wsm    = (float*)(smem + OFF_WSM);

    if (tid < HID_) {
        float s = 0.f;
        #pragma unroll
        for (int c = 0; c < KC_; c++) s += g_part[c][b][tid];
        bias_s[tid] = s;
        w2_s[tid]   = W2[tid];
    }

    // acc2[hj][pi]: f32x2 over p-pair (2pi, 2pi+1) at h = tx*4 + hj
    u64 acc2[4][4];
    #pragma unroll
    for (int j = 0; j < 4; j++)
        #pragma unroll
        for (int i = 0; i < 4; i++) acc2[j][i] = 0ull;

    const float* kb = keys + (size_t)b * P_ * KD;

    float4 aP[4], bP[2];
    // LDG chunk 0 -> regs
    #pragma unroll
    for (int i = 0; i < 4; i++) {
        int fid = tid + 256 * i;
        int p = fid >> 3, kq = (fid & 7) << 2;
        aP[i] = *reinterpret_cast<const float4*>(kb + (size_t)p * KD + kq);
    }
    #pragma unroll
    for (int i = 0; i < 2; i++) {
        int fid = tid + 256 * i;
        int kk = fid >> 4, h4 = (fid & 15) << 2;
        bP[i] = *reinterpret_cast<const float4*>(W1 + (size_t)kk * HID_ + h4);
    }
    // STS chunk 0 -> stage 0 (B pre-duplicated)
    {
        float* sA0 = (float*)(smem + OFF_SA(0));
        u64*   sB0 = (u64*)(smem + OFF_SB2(0));
        #pragma unroll
        for (int i = 0; i < 4; i++) {
            int fid = tid + 256 * i;
            int p = fid >> 3, kq = (fid & 7) << 2;
            sA0[(kq + 0) * SA_STRIDE + p] = aP[i].x;
            sA0[(kq + 1) * SA_STRIDE + p] = aP[i].y;
            sA0[(kq + 2) * SA_STRIDE + p] = aP[i].z;
            sA0[(kq + 3) * SA_STRIDE + p] = aP[i].w;
        }
        #pragma unroll
        for (int i = 0; i < 2; i++) {
            int fid = tid + 256 * i;
            int kk = fid >> 4, h4 = (fid & 15) << 2;
            ulonglong2 v0 = make_ulonglong2(dup2(bP[i].x), dup2(bP[i].y));
            ulonglong2 v1 = make_ulonglong2(dup2(bP[i].z), dup2(bP[i].w));
            *reinterpret_cast<ulonglong2*>(&sB0[kk * 64 + h4])     = v0;
            *reinterpret_cast<ulonglong2*>(&sB0[kk * 64 + h4 + 2]) = v1;
        }
    }
    // LDG chunk 1 -> regs
    #pragma unroll
    for (int i = 0; i < 4; i++) {
        int fid = tid + 256 * i;
        int p = fid >> 3, kq = (fid & 7) << 2;
        aP[i] = *reinterpret_cast<const float4*>(kb + (size_t)p * KD + 32 + kq);
    }
    #pragma unroll
    for (int i = 0; i < 2; i++) {
        int fid = tid + 256 * i;
        int kk = fid >> 4, h4 = (fid & 15) << 2;
        bP[i] = *reinterpret_cast<const float4*>(W1 + (size_t)(32 + kk) * HID_ + h4);
    }
    __syncthreads();

    for (int c = 0; c < 16; c++) {
        const int s = c & 1;
        // STS chunk c+1 (in regs) -> stage s^1
        if (c < 15) {
            float* sAn = (float*)(smem + OFF_SA(s ^ 1));
            u64*   sBn = (u64*)(smem + OFF_SB2(s ^ 1));
            #pragma unroll
            for (int i = 0; i < 4; i++) {
                int fid = tid + 256 * i;
                int p = fid >> 3, kq = (fid & 7) << 2;
                sAn[(kq + 0) * SA_STRIDE + p] = aP[i].x;
                sAn[(kq + 1) * SA_STRIDE + p] = aP[i].y;
                sAn[(kq + 2) * SA_STRIDE + p] = aP[i].z;
                sAn[(kq + 3) * SA_STRIDE + p] = aP[i].w;
            }
            #pragma unroll
            for (int i = 0; i < 2; i++) {
                int fid = tid + 256 * i;
                int kk = fid >> 4, h4 = (fid & 15) << 2;
                ulonglong2 v0 = make_ulonglong2(dup2(bP[i].x), dup2(bP[i].y));
                ulonglong2 v1 = make_ulonglong2(dup2(bP[i].z), dup2(bP[i].w));
                *reinterpret_cast<ulonglong2*>(&sBn[kk * 64 + h4])     = v0;
                *reinterpret_cast<ulonglong2*>(&sBn[kk * 64 + h4 + 2]) = v1;
            }
        }
        // LDG chunk c+2 -> regs
        if (c < 14) {
            int k0 = (c + 2) * 32;
            #pragma unroll
            for (int i = 0; i < 4; i++) {
                int fid = tid + 256 * i;
                int p = fid >> 3, kq = (fid & 7) << 2;
                aP[i] = *reinterpret_cast<const float4*>(kb + (size_t)p * KD + k0 + kq);
            }
            #pragma unroll
            for (int i = 0; i < 2; i++) {
                int fid = tid + 256 * i;
                int kk = fid >> 4, h4 = (fid & 15) << 2;
                bP[i] = *reinterpret_cast<const float4*>(W1 + (size_t)(k0 + kk) * HID_ + h4);
            }
        }
        // compute stage s: 4 LDS.128 + 16 FFMA2 per kk
        const float* sA  = (const float*)(smem + OFF_SA(s));
        const u64*   sB2 = (const u64*)(smem + OFF_SB2(s));
        #pragma unroll 8
        for (int kk = 0; kk < 32; kk++) {
            ulonglong2 a01 = *reinterpret_cast<const ulonglong2*>(&sA[kk * SA_STRIDE + (ty << 3)]);
            ulonglong2 a23 = *reinterpret_cast<const ulonglong2*>(&sA[kk * SA_STRIDE + (ty << 3) + 4]);
            ulonglong2 b01 = *reinterpret_cast<const ulonglong2*>(&sB2[kk * 64 + (tx << 2)]);
            ulonglong2 b23 = *reinterpret_cast<const ulonglong2*>(&sB2[kk * 64 + (tx << 2) + 2]);
            u64 ap0 = a01.x, ap1 = a01.y, ap2 = a23.x, ap3 = a23.y;
            acc2[0][0] = ffma2(ap0, b01.x, acc2[0][0]);
            acc2[0][1] = ffma2(ap1, b01.x, acc2[0][1]);
            acc2[0][2] = ffma2(ap2, b01.x, acc2[0][2]);
            acc2[0][3] = ffma2(ap3, b01.x, acc2[0][3]);
            acc2[1][0] = ffma2(ap0, b01.y, acc2[1][0]);
            acc2[1][1] = ffma2(ap1, b01.y, acc2[1][1]);
            acc2[1][2] = ffma2(ap2, b01.y, acc2[1][2]);
            acc2[1][3] = ffma2(ap3, b01.y, acc2[1][3]);
            acc2[2][0] = ffma2(ap0, b23.x, acc2[2][0]);
            acc2[2][1] = ffma2(ap1, b23.x, acc2[2][1]);
            acc2[2][2] = ffma2(ap2, b23.x, acc2[2][2]);
            acc2[2][3] = ffma2(ap3, b23.x, acc2[2][3]);
            acc2[3][0] = ffma2(ap0, b23.y, acc2[3][0]);
            acc2[3][1] = ffma2(ap1, b23.y, acc2[3][1]);
            acc2[3][2] = ffma2(ap2, b23.y, acc2[3][2]);
            acc2[3][3] = ffma2(ap3, b23.y, acc2[3][3]);
        }
        __syncthreads();
    }

    // Epilogue: bias + relu + W2 partial dot. lo(acc)=p even, hi=p odd.
    // red aliases stage-0 sA, which is dead (last chunk computed stage 1).
    float* red = (float*)(smem + OFF_RED);
    const int h0 = tx << 2;
    #pragma unroll
    for (int pi = 0; pi < 4; pi++) {
        float s0 = 0.f, s1 = 0.f;
        #pragma unroll
        for (int hj = 0; hj < 4; hj++) {
            float lo, hi;
            unpack2(acc2[hj][pi], lo, hi);
            float bz = bias_s[h0 + hj];
            float wz = w2_s[h0 + hj];
            s0 = fmaf(fmaxf(lo + bz, 0.f), wz, s0);
            s1 = fmaf(fmaxf(hi + bz, 0.f), wz, s1);
        }
        red[((ty << 3) + 2 * pi)     * 17 + tx] = s0;
        red[((ty << 3) + 2 * pi + 1) * 17 + tx] = s1;
    }
    __syncthreads();

    // scores for p = tid (first 128 threads), masked softmax
    float score = -CUDART_INF_F;
    int mv = 0;
    if (tid < P_) {
        float s = 0.f;
        #pragma unroll
        for (int x = 0; x < 16; x++) s += red[tid * 17 + x];
        mv = mask[b * P_ + tid];
        score = mv ? s : -CUDART_INF_F;
    }
    float m = score;
    #pragma unroll
    for (int o = 16; o > 0; o >>= 1)
        m = fmaxf(m, __shfl_xor_sync(0xffffffffu, m, o));
    if (tid < P_ && (tid & 31) == 0) rtmp[tid >> 5] = m;
    __syncthreads();
    float mx = fmaxf(fmaxf(rtmp[0], rtmp[1]), fmaxf(rtmp[2], rtmp[3]));
    __syncthreads();

    float e = (tid < P_ && mv) ? expf(score - mx) : 0.f;
    float ssum = e;
    #pragma unroll
    for (int o = 16; o > 0; o >>= 1)
        ssum += __shfl_xor_sync(0xffffffffu, ssum, o);
    if (tid < P_ && (tid & 31) == 0) rtmp[tid >> 5] = ssum;
    __syncthreads();
    float total = rtmp[0] + rtmp[1] + rtmp[2] + rtmp[3];

    float* weights_out = out + (size_t)B_ * EMB;
    if (tid < P_) {
        float wv = e / total;
        weights_out[b * P_ + tid] = wv;
        wsm[tid] = wv;
    }
    __syncthreads();

    // Fused context: thread t -> cols 2t, 2t+1 (keys L2-hot from GEMM pass)
    float cx = 0.f, cy = 0.f;
    const float* kcol = kb + 2 * tid;
    #pragma unroll 8
    for (int p = 0; p < P_; p++) {
        float2 kv = *reinterpret_cast<const float2*>(kcol + (size_t)p * KD);
        float wp = wsm[p];
        cx = fmaf(wp, kv.x, cx);
        cy = fmaf(wp, kv.y, cy);
    }
    float* ob = out + (size_t)b * EMB;
    *reinterpret_cast<float2*>(ob + 2 * tid) = make_float2(cx, cy);

    // frame concat: 1024 floats = 256 float4, one per thread
    const float* fb = frame + (size_t)b * (2 * HF_);
    *reinterpret_cast<float4*>(ob + KD + 4 * tid) =
        *reinterpret_cast<const float4*>(fb + 4 * tid);
}

// ---------------------------------------------------------------------------
extern "C" void kernel_launch(void* const* d_in, const int* in_sizes, int n_in,
                              void* d_out, int out_size)
{
    const float* query = (const float*)d_in[0];   // (256,1,1024)
    const float* keys  = (const float*)d_in[1];   // (256,128,512)
    const float* frame = (const float*)d_in[2];   // (256,1,1024)
    const int*   mask  = (const int*)  d_in[3];   // (256,128)
    const float* W1    = (const float*)d_in[4];   // (2560,64)
    const float* W2    = (const float*)d_in[5];   // (64,1)

    float* out = (float*)d_out;

    cudaFuncSetAttribute(score_kernel,
                         cudaFuncAttributeMaxDynamicSharedMemorySize, SMEM_DYN);

    dim3 bgrid(KC_, BG_);
    bias_kernel <<<bgrid, 256>>>(query, frame, W1);
    score_kernel<<<B_, 256, SMEM_DYN>>>(keys, frame, mask, W1, W2, out);
}